// round 7
// baseline (speedup 1.0000x reference)
#include <cuda_runtime.h>
#include <cuda_bf16.h>
#include <math.h>
#include <stdint.h>

// ---------------------------------------------------------------------------
// DiT block. Round 7: GEMM retiled to 64x128 / 128-thread CTAs (4-warp
// barriers, 3 CTAs/SM) to cut barrier-convergence stalls; to_k/to_v merged.
// ---------------------------------------------------------------------------

#define Bsz   8
#define Ntok  1024
#define Hdim  1152
#define NHead 16
#define HeadD 72
#define CtxD  768
#define CtxT  77
#define MlpD  4608
#define Mrows (Bsz * Ntok)     // 8192
#define Crows (Bsz * CtxT)     // 616
#define ModW  (6 * Hdim)       // 6912
#define KVW   (2 * Hdim)       // 2304 (merged k|v width)

typedef __nv_bfloat16 bf16;
typedef __nv_bfloat162 bf162;

// ------------------------- scratch (no allocations) ------------------------
__device__ float g_mod [Bsz * ModW];
__device__ float g_xb  [Mrows * Hdim];

__device__ bf16 g_ln_h [Mrows * Hdim],  g_ln_l [Mrows * Hdim];
__device__ bf16 g_at_h [Mrows * Hdim],  g_at_l [Mrows * Hdim];
__device__ bf16 g_xb_h [Mrows * Hdim],  g_xb_l [Mrows * Hdim];
__device__ bf16 g_qkv_h[Mrows * 3 * Hdim], g_qkv_l[Mrows * 3 * Hdim];
__device__ bf16 g_kv_h [Crows * KVW],   g_kv_l [Crows * KVW];
__device__ bf16 g_hid_h[Mrows * MlpD],  g_hid_l[Mrows * MlpD];
__device__ bf16 g_c_h  [Crows * CtxD],  g_c_l  [Crows * CtxD];
__device__ bf16 g_wqkv_h[3 * Hdim * Hdim], g_wqkv_l[3 * Hdim * Hdim];
__device__ bf16 g_wpr_h [Hdim * Hdim],     g_wpr_l [Hdim * Hdim];
__device__ bf16 g_wq_h  [Hdim * Hdim],     g_wq_l  [Hdim * Hdim];
__device__ bf16 g_wkv_h [KVW * CtxD],      g_wkv_l [KVW * CtxD];
__device__ bf16 g_wo_h  [Hdim * Hdim],     g_wo_l  [Hdim * Hdim];
__device__ bf16 g_w1_h  [MlpD * Hdim],     g_w1_l  [MlpD * Hdim];
__device__ bf16 g_w2_h  [Hdim * MlpD],     g_w2_l  [Hdim * MlpD];

// ------------------------------ helpers ------------------------------------
__device__ __forceinline__ void split_bf16(float v, bf16& h, bf16& l) {
  h = __float2bfloat16(v);
  l = __float2bfloat16(v - __bfloat162float(h));
}
__device__ __forceinline__ float ex2(float x) {
  float y; asm("ex2.approx.f32 %0, %1;" : "=f"(y) : "f"(x)); return y;
}
__device__ __forceinline__ uint32_t prmt_hi(uint32_t a, uint32_t b) {
  uint32_t d; asm("prmt.b32 %0,%1,%2,0x7632;" : "=r"(d) : "r"(a), "r"(b));
  return d;
}
__device__ __forceinline__ uint32_t pack_bf2(float lo, float hi) {
  uint32_t d;
  asm("cvt.rn.bf16x2.f32 %0, %1, %2;" : "=r"(d) : "f"(hi), "f"(lo));
  return d;
}
__device__ __forceinline__ float truncf_bf(float x) {
  return __uint_as_float(__float_as_uint(x) & 0xFFFF0000u);
}

// -------------------- fused weight/context conversion ----------------------
struct CvtJobs {
  const float* src[9];
  bf16* hi[9];
  bf16* lo[9];
  int n[9];
};

__global__ __launch_bounds__(256) void cvt_all_kernel(CvtJobs J) {
  int t = blockIdx.y;
  int i = (blockIdx.x * 256 + threadIdx.x) * 4;
  if (i >= J.n[t]) return;
  float4 v = *(const float4*)(J.src[t] + i);
  bf16 h0, l0, h1, l1, h2, l2, h3, l3;
  split_bf16(v.x, h0, l0); split_bf16(v.y, h1, l1);
  split_bf16(v.z, h2, l2); split_bf16(v.w, h3, l3);
  bf16* hi = J.hi[t]; bf16* lo = J.lo[t];
  *(bf162*)(hi + i)     = __halves2bfloat162(h0, h1);
  *(bf162*)(hi + i + 2) = __halves2bfloat162(h2, h3);
  *(bf162*)(lo + i)     = __halves2bfloat162(l0, l1);
  *(bf162*)(lo + i + 2) = __halves2bfloat162(l2, l3);
}

// --------------------------- adaLN modulation ------------------------------
__global__ __launch_bounds__(128) void ada_kernel(
    const float* __restrict__ t_emb, const float* __restrict__ ada_w,
    const float* __restrict__ ada_b, float* __restrict__ mod) {
  __shared__ float se[Bsz * Hdim];
  int tid = threadIdx.x;
  for (int i = tid; i < Bsz * Hdim; i += 128) {
    float v = t_emb[i];
    se[i] = v / (1.f + __expf(-v));
  }
  __syncthreads();
  int j = blockIdx.x * 128 + tid;
  const float* w = ada_w + (size_t)j * Hdim;
  float acc[Bsz];
#pragma unroll
  for (int b = 0; b < Bsz; b++) acc[b] = 0.f;
  for (int k = 0; k < Hdim; k += 4) {
    float4 wv = *(const float4*)(w + k);
#pragma unroll
    for (int b = 0; b < Bsz; b++) {
      const float* s = se + b * Hdim + k;
      acc[b] += wv.x * s[0] + wv.y * s[1] + wv.z * s[2] + wv.w * s[3];
    }
  }
  float bb = ada_b[j];
#pragma unroll
  for (int b = 0; b < Bsz; b++) mod[b * ModW + j] = acc[b] + bb;
}

// ----------------- LayerNorm + modulate -> bf16 hi/lo -----------------------
__global__ __launch_bounds__(256) void ln_mod_kernel(
    const float* __restrict__ x, const float* __restrict__ mod,
    int sh_off, int sc_off, bf16* __restrict__ ohi, bf16* __restrict__ olo) {
  int row = blockIdx.x;
  int b = row >> 10;
  const float* xr = x + (size_t)row * Hdim;
  int tid = threadIdx.x;
  float s = 0.f, ss = 0.f;
  for (int i = tid; i < Hdim; i += 256) {
    float v = xr[i];
    s += v; ss += v * v;
  }
#pragma unroll
  for (int o = 16; o > 0; o >>= 1) {
    s  += __shfl_xor_sync(0xffffffffu, s, o);
    ss += __shfl_xor_sync(0xffffffffu, ss, o);
  }
  __shared__ float rs[8], rss[8], stat[2];
  int w = tid >> 5;
  if ((tid & 31) == 0) { rs[w] = s; rss[w] = ss; }
  __syncthreads();
  if (tid == 0) {
    float S = 0.f, SS = 0.f;
#pragma unroll
    for (int i = 0; i < 8; i++) { S += rs[i]; SS += rss[i]; }
    float mu = S * (1.f / Hdim);
    float var = SS * (1.f / Hdim) - mu * mu;
    stat[0] = mu;
    stat[1] = rsqrtf(var + 1e-6f);
  }
  __syncthreads();
  float mu = stat[0], rstd = stat[1];
  const float* sh = mod + b * ModW + sh_off * Hdim;
  const float* sc = mod + b * ModW + sc_off * Hdim;
  bf16* oh = ohi + (size_t)row * Hdim;
  bf16* ol = olo + (size_t)row * Hdim;
  for (int i = tid; i < Hdim; i += 256) {
    float v = (xr[i] - mu) * rstd * (1.f + sc[i]) + sh[i];
    bf16 h, l; split_bf16(v, h, l);
    oh[i] = h; ol[i] = l;
  }
}

// ------------------- tensor-core GEMM (NT, bf16 x3) -------------------------
__device__ __forceinline__ float gelu_tanh(float v) {
  const float c = 0.7978845608028654f;
  return 0.5f * v * (1.f + tanhf(c * (v + 0.044715f * v * v * v)));
}

#define EPI_BIAS    0
#define EPI_GELU    1
#define EPI_RESGATE 2

__device__ __forceinline__ void mma_bf16(float c[4], const uint32_t a[4],
                                         const uint32_t b[2]) {
  asm volatile(
      "mma.sync.aligned.m16n8k16.row.col.f32.bf16.bf16.f32 "
      "{%0,%1,%2,%3}, {%4,%5,%6,%7}, {%8,%9}, {%0,%1,%2,%3};"
      : "+f"(c[0]), "+f"(c[1]), "+f"(c[2]), "+f"(c[3])
      : "r"(a[0]), "r"(a[1]), "r"(a[2]), "r"(a[3]), "r"(b[0]), "r"(b[1]));
}

__device__ __forceinline__ void ldsm4(uint32_t r[4], uint32_t addr) {
  asm volatile("ldmatrix.sync.aligned.m8n8.x4.shared.b16 {%0,%1,%2,%3}, [%4];"
               : "=r"(r[0]), "=r"(r[1]), "=r"(r[2]), "=r"(r[3]) : "r"(addr));
}
__device__ __forceinline__ void ldsm4t(uint32_t r[4], uint32_t addr) {
  asm volatile(
      "ldmatrix.sync.aligned.m8n8.x4.trans.shared.b16 {%0,%1,%2,%3}, [%4];"
      : "=r"(r[0]), "=r"(r[1]), "=r"(r[2]), "=r"(r[3]) : "r"(addr));
}

__device__ __forceinline__ void cp16(uint32_t dst, const void* src, bool p) {
  int sz = p ? 16 : 0;
  asm volatile("cp.async.cg.shared.global [%0], [%1], 16, %2;\n"
               :: "r"(dst), "l"(src), "r"(sz));
}

// 64x128 tile: A plane 64 rows x 80B, B plane 128 rows x 80B.
#define TA_B    5120
#define TB_B    10240
#define STAGE_B (2 * TA_B + 2 * TB_B)    // 30720
#define GSMEM   (2 * STAGE_B)            // 61440

template <int EPI, bool OUTF, bool OUTB>
__global__ __launch_bounds__(128, 3) void gemm_tc(
    const bf16* __restrict__ Ah, const bf16* __restrict__ Al,
    const bf16* __restrict__ Wh, const bf16* __restrict__ Wl,
    const float* __restrict__ bias, const float* __restrict__ res,
    const float* __restrict__ gate, float* __restrict__ C,
    bf16* __restrict__ Chi, bf16* __restrict__ Clo,
    int M, int N, int K) {
  extern __shared__ char smc[];
  uint32_t sbase = (uint32_t)__cvta_generic_to_shared(smc);
  int tid = threadIdx.x;
  int warp = tid >> 5, lane = tid & 31;
  int wm = warp & 1, wn = warp >> 1;     // 2 warps M x 2 warps N
  int m0 = blockIdx.y << 6, n0 = blockIdx.x << 7;

  float acc[2][8][4];
#pragma unroll
  for (int mt = 0; mt < 2; mt++)
#pragma unroll
    for (int nt = 0; nt < 8; nt++)
#pragma unroll
      for (int f = 0; f < 4; f++) acc[mt][nt][f] = 0.f;

  int lq = lane & 7, lb = (lane >> 3) & 1, lh = lane >> 4;
  uint32_t offA[2], offB[4];
#pragma unroll
  for (int mt = 0; mt < 2; mt++)
    offA[mt] = (uint32_t)((wm * 32 + mt * 16 + lq + lb * 8) * 80 + lh * 16);
#pragma unroll
  for (int j = 0; j < 4; j++)
    offB[j] = (uint32_t)(2 * TA_B +
                         (wn * 64 + j * 16 + lq + lh * 8) * 80 + lb * 16);

  const int nk = K >> 5;

  // 1536 16B chunks per stage: A(2 planes x 256) then B(2 planes x 512).
  auto issue = [&](int k0, int s) {
    uint32_t st = sbase + s * STAGE_B;
#pragma unroll
    for (int i = 0; i < 12; i++) {
      int idx = tid + (i << 7);
      uint32_t d; const bf16* src; bool ok = true;
      if (idx < 512) {
        int pl = idx >> 8, cc = idx & 255;
        int row = cc >> 2, ch = cc & 3;
        int gm = m0 + row;
        ok = gm < M;
        src = (pl ? Al : Ah) + (size_t)(ok ? gm : 0) * K + k0 + ch * 8;
        d = st + pl * TA_B + row * 80 + ch * 16;
      } else {
        int ib = idx - 512;
        int pl = ib >> 9, cc = ib & 511;
        int row = cc >> 2, ch = cc & 3;
        src = (pl ? Wl : Wh) + (size_t)(n0 + row) * K + k0 + ch * 8;
        d = st + 2 * TA_B + pl * TB_B + row * 80 + ch * 16;
      }
      cp16(d, src, ok);
    }
    asm volatile("cp.async.commit_group;\n");
  };

  issue(0, 0);
  for (int kt = 0; kt < nk; kt++) {
    int s = kt & 1;
    if (kt + 1 < nk) {
      issue((kt + 1) << 5, s ^ 1);
      asm volatile("cp.async.wait_group 1;\n");
    } else {
      asm volatile("cp.async.wait_group 0;\n");
    }
    __syncthreads();

    uint32_t sb = sbase + s * STAGE_B;
#pragma unroll
    for (int ks = 0; ks < 2; ks++) {
      uint32_t ah[2][4], al[2][4];
#pragma unroll
      for (int mt = 0; mt < 2; mt++) {
        ldsm4(ah[mt], sb + offA[mt] + ks * 32);
        ldsm4(al[mt], sb + offA[mt] + TA_B + ks * 32);
      }
#pragma unroll
      for (int jp = 0; jp < 2; jp++) {
        uint32_t bh0[4], bl0[4], bh1[4], bl1[4];
        ldsm4(bh0, sb + offB[2 * jp]     + ks * 32);
        ldsm4(bl0, sb + offB[2 * jp]     + TB_B + ks * 32);
        ldsm4(bh1, sb + offB[2 * jp + 1] + ks * 32);
        ldsm4(bl1, sb + offB[2 * jp + 1] + TB_B + ks * 32);
        float (*a0)[4] = acc[0], (*a1)[4] = acc[1];
        int n0i = 4 * jp;
        mma_bf16(a0[n0i],     ah[0], bh0);
        mma_bf16(a0[n0i + 1], ah[0], bh0 + 2);
        mma_bf16(a1[n0i],     ah[1], bh0);
        mma_bf16(a1[n0i + 1], ah[1], bh0 + 2);
        mma_bf16(a0[n0i + 2], ah[0], bh1);
        mma_bf16(a0[n0i + 3], ah[0], bh1 + 2);
        mma_bf16(a1[n0i + 2], ah[1], bh1);
        mma_bf16(a1[n0i + 3], ah[1], bh1 + 2);
        mma_bf16(a0[n0i],     ah[0], bl0);
        mma_bf16(a0[n0i + 1], ah[0], bl0 + 2);
        mma_bf16(a1[n0i],     ah[1], bl0);
        mma_bf16(a1[n0i + 1], ah[1], bl0 + 2);
        mma_bf16(a0[n0i + 2], ah[0], bl1);
        mma_bf16(a0[n0i + 3], ah[0], bl1 + 2);
        mma_bf16(a1[n0i + 2], ah[1], bl1);
        mma_bf16(a1[n0i + 3], ah[1], bl1 + 2);
        mma_bf16(a0[n0i],     al[0], bh0);
        mma_bf16(a0[n0i + 1], al[0], bh0 + 2);
        mma_bf16(a1[n0i],     al[1], bh0);
        mma_bf16(a1[n0i + 1], al[1], bh0 + 2);
        mma_bf16(a0[n0i + 2], al[0], bh1);
        mma_bf16(a0[n0i + 3], al[0], bh1 + 2);
        mma_bf16(a1[n0i + 2], al[1], bh1);
        mma_bf16(a1[n0i + 3], al[1], bh1 + 2);
      }
    }
    __syncthreads();
  }

  int g = lane >> 2, tg = lane & 3;
#pragma unroll
  for (int mt = 0; mt < 2; mt++) {
#pragma unroll
    for (int half = 0; half < 2; half++) {
      int m = m0 + wm * 32 + mt * 16 + g + half * 8;
      if (m >= M) continue;
      int bq = m >> 10;
#pragma unroll
      for (int nt = 0; nt < 8; nt++) {
        int n = n0 + wn * 64 + nt * 8 + tg * 2;
        float v0 = acc[mt][nt][half * 2 + 0];
        float v1 = acc[mt][nt][half * 2 + 1];
        if (bias) { v0 += bias[n]; v1 += bias[n + 1]; }
        if (EPI == EPI_GELU) { v0 = gelu_tanh(v0); v1 = gelu_tanh(v1); }
        if (EPI == EPI_RESGATE) {
          float g0 = 1.f, g1 = 1.f;
          if (gate) { g0 = gate[bq * ModW + n]; g1 = gate[bq * ModW + n + 1]; }
          v0 = res[(size_t)m * N + n] + g0 * v0;
          v1 = res[(size_t)m * N + n + 1] + g1 * v1;
        }
        if (OUTF)
          *(float2*)(C + (size_t)m * N + n) = make_float2(v0, v1);
        if (OUTB) {
          bf16 h0, l0, h1, l1;
          split_bf16(v0, h0, l0);
          split_bf16(v1, h1, l1);
          *(bf162*)(Chi + (size_t)m * N + n) = __halves2bfloat162(h0, h1);
          *(bf162*)(Clo + (size_t)m * N + n) = __halves2bfloat162(l0, l1);
        }
      }
    }
  }
}

// ---------------- tensor-core flash attention (bf16 x3) ---------------------
#define ARB   176
#define APL   (128 * ARB)
#define AKVST (4 * APL)
#define ATSM  (2 * APL + 2 * AKVST)

__global__ __launch_bounds__(256) void attn_tc(
    const bf16* __restrict__ Qh, const bf16* __restrict__ Ql,
    long long qbs, int ldq,
    const bf16* __restrict__ Kh, const bf16* __restrict__ Kl,
    const bf16* __restrict__ Vh, const bf16* __restrict__ Vl,
    long long kbs, int ldk,
    bf16* __restrict__ Oh, bf16* __restrict__ Ol,
    int kv_len, float sl2e) {
  extern __shared__ char smb[];
  uint32_t sb = (uint32_t)__cvta_generic_to_shared(smb);
  int b = blockIdx.z, h = blockIdx.y;
  int m0 = blockIdx.x * 128;
  int tid = threadIdx.x, warp = tid >> 5, lane = tid & 31;
  int g = lane >> 2, tg = lane & 3;
  int lq = lane & 7, lb = (lane >> 3) & 1, lh = lane >> 4;

  const bf16* Qhb = Qh + (size_t)b * qbs + (size_t)m0 * ldq + h * HeadD;
  const bf16* Qlb = Ql + (size_t)b * qbs + (size_t)m0 * ldq + h * HeadD;
  const bf16* Khb = Kh + (size_t)b * kbs + h * HeadD;
  const bf16* Klb = Kl + (size_t)b * kbs + h * HeadD;
  const bf16* Vhb = Vh + (size_t)b * kbs + h * HeadD;
  const bf16* Vlb = Vl + (size_t)b * kbs + h * HeadD;

  for (int i = tid; i < 1280; i += 256) {
    int p = i >> 7, r = i & 127;
    uint32_t ad = sb + p * APL + r * ARB + 144;
    asm volatile("st.shared.v4.b32 [%0], {%1,%1,%1,%1};" :: "r"(ad), "r"(0));
    asm volatile("st.shared.v4.b32 [%0], {%1,%1,%1,%1};"
                 :: "r"(ad + 16), "r"(0));
  }

  for (int i = tid; i < 1152; i += 256) {
    int r = i / 9, ch = i % 9;
    uint32_t d = sb + r * ARB + ch * 16;
    cp16(d,       Qhb + (size_t)r * ldq + ch * 8, true);
    cp16(d + APL, Qlb + (size_t)r * ldq + ch * 8, true);
  }

  auto loadKV = [&](int j0, int s) {
    uint32_t st = sb + 2 * APL + s * AKVST;
    for (int i = tid; i < 1152; i += 256) {
      int r = i / 9, ch = i % 9;
      bool ok = (j0 + r) < kv_len;
      int rc = ok ? (j0 + r) : 0;
      size_t off = (size_t)rc * ldk + ch * 8;
      uint32_t d = st + r * ARB + ch * 16;
      cp16(d,           Khb + off, ok);
      cp16(d + APL,     Klb + off, ok);
      cp16(d + 2 * APL, Vhb + off, ok);
      cp16(d + 3 * APL, Vlb + off, ok);
    }
    asm volatile("cp.async.commit_group;\n");
  };

  int iters = (kv_len + 127) >> 7;
  loadKV(0, 0);
  if (iters > 1) loadKV(128, 1);

  float m0r = -1e30f, m1r = -1e30f, ls0 = 0.f, ls1 = 0.f;
  float oacc[9][4];
#pragma unroll
  for (int nt = 0; nt < 9; nt++)
#pragma unroll
    for (int f = 0; f < 4; f++) oacc[nt][f] = 0.f;

  uint32_t offA = (uint32_t)((warp * 16 + lq + lb * 8) * ARB + lh * 16);
  uint32_t offB = (uint32_t)((lq + lh * 8) * ARB + lb * 16);
  uint32_t offV = (uint32_t)((lq + lb * 8) * ARB + lh * 16);

  for (int it = 0; it < iters; it++) {
    if (it + 1 < iters) {
      if (it > 0) loadKV((it + 1) * 128, (it + 1) & 1);
      asm volatile("cp.async.wait_group 1;\n");
    } else {
      asm volatile("cp.async.wait_group 0;\n");
    }
    __syncthreads();

    uint32_t kbse = sb + 2 * APL + (it & 1) * AKVST;

    float sa[16][4];
#pragma unroll
    for (int j = 0; j < 16; j++)
#pragma unroll
      for (int f = 0; f < 4; f++) sa[j][f] = 0.f;

#pragma unroll
    for (int ks = 0; ks < 5; ks++) {
      uint32_t ah[4], al_[4];
      ldsm4(ah,  sb + offA + ks * 32);
      ldsm4(al_, sb + APL + offA + ks * 32);
#pragma unroll
      for (int ntp = 0; ntp < 4; ntp++) {
        uint32_t bh0[4], bl0[4], bh1[4], bl1[4];
        ldsm4(bh0, kbse + offB + (2 * ntp) * 16 * ARB + ks * 32);
        ldsm4(bl0, kbse + APL + offB + (2 * ntp) * 16 * ARB + ks * 32);
        ldsm4(bh1, kbse + offB + (2 * ntp + 1) * 16 * ARB + ks * 32);
        ldsm4(bl1, kbse + APL + offB + (2 * ntp + 1) * 16 * ARB + ks * 32);
        int q = 4 * ntp;
        mma_bf16(sa[q],     ah, bh0);
        mma_bf16(sa[q + 1], ah, bh0 + 2);
        mma_bf16(sa[q + 2], ah, bh1);
        mma_bf16(sa[q + 3], ah, bh1 + 2);
        mma_bf16(sa[q],     ah, bl0);
        mma_bf16(sa[q + 1], ah, bl0 + 2);
        mma_bf16(sa[q + 2], ah, bl1);
        mma_bf16(sa[q + 3], ah, bl1 + 2);
        mma_bf16(sa[q],     al_, bh0);
        mma_bf16(sa[q + 1], al_, bh0 + 2);
        mma_bf16(sa[q + 2], al_, bh1);
        mma_bf16(sa[q + 3], al_, bh1 + 2);
      }
    }

    int j0 = it * 128;
    bool msk = (j0 + 128) > kv_len;
    float mx0 = -1e30f, mx1 = -1e30f;
#pragma unroll
    for (int j = 0; j < 16; j++) {
#pragma unroll
      for (int e = 0; e < 4; e++) {
        float v = sa[j][e] * sl2e;
        if (msk) {
          int col = j * 8 + 2 * tg + (e & 1);
          if (j0 + col >= kv_len) v = -1e30f;
        }
        sa[j][e] = v;
      }
      mx0 = fmaxf(mx0, fmaxf(sa[j][0], sa[j][1]));
      mx1 = fmaxf(mx1, fmaxf(sa[j][2], sa[j][3]));
    }
    mx0 = fmaxf(mx0, __shfl_xor_sync(0xffffffffu, mx0, 1));
    mx0 = fmaxf(mx0, __shfl_xor_sync(0xffffffffu, mx0, 2));
    mx1 = fmaxf(mx1, __shfl_xor_sync(0xffffffffu, mx1, 1));
    mx1 = fmaxf(mx1, __shfl_xor_sync(0xffffffffu, mx1, 2));
    float mn0 = fmaxf(m0r, mx0), mn1 = fmaxf(m1r, mx1);
    float al0 = ex2(m0r - mn0), al1 = ex2(m1r - mn1);
    m0r = mn0; m1r = mn1;

    float s0 = 0.f, s1 = 0.f;
#pragma unroll
    for (int j = 0; j < 16; j++) {
      float p0 = ex2(sa[j][0] - mn0), p1 = ex2(sa[j][1] - mn0);
      float p2 = ex2(sa[j][2] - mn1), p3 = ex2(sa[j][3] - mn1);
      sa[j][0] = p0; sa[j][1] = p1; sa[j][2] = p2; sa[j][3] = p3;
      s0 += p0 + p1; s1 += p2 + p3;
    }
    s0 += __shfl_xor_sync(0xffffffffu, s0, 1);
    s0 += __shfl_xor_sync(0xffffffffu, s0, 2);
    s1 += __shfl_xor_sync(0xffffffffu, s1, 1);
    s1 += __shfl_xor_sync(0xffffffffu, s1, 2);
    ls0 = ls0 * al0 + s0;
    ls1 = ls1 * al1 + s1;
#pragma unroll
    for (int nt = 0; nt < 9; nt++) {
      oacc[nt][0] *= al0; oacc[nt][1] *= al0;
      oacc[nt][2] *= al1; oacc[nt][3] *= al1;
    }

    uint32_t vbse = kbse + 2 * APL;
#pragma unroll
    for (int kc = 0; kc < 8; kc++) {
      uint32_t pah[4], pal[4];
#pragma unroll
      for (int jj = 0; jj < 2; jj++) {
        int j = 2 * kc + jj;
        uint32_t u0 = __float_as_uint(sa[j][0]);
        uint32_t u1 = __float_as_uint(sa[j][1]);
        uint32_t u2 = __float_as_uint(sa[j][2]);
        uint32_t u3 = __float_as_uint(sa[j][3]);
        pah[2 * jj]     = prmt_hi(u0, u1);
        pah[2 * jj + 1] = prmt_hi(u2, u3);
        pal[2 * jj]     = pack_bf2(sa[j][0] - truncf_bf(sa[j][0]),
                                   sa[j][1] - truncf_bf(sa[j][1]));
        pal[2 * jj + 1] = pack_bf2(sa[j][2] - truncf_bf(sa[j][2]),
                                   sa[j][3] - truncf_bf(sa[j][3]));
      }
#pragma unroll
      for (int npp = 0; npp < 2; npp++) {
        int np0 = 2 * npp, np1 = 2 * npp + 1;
        uint32_t vh0[4], vl0[4], vh1[4], vl1[4];
        ldsm4t(vh0, vbse + offV + kc * 16 * ARB + np0 * 32);
        ldsm4t(vl0, vbse + APL + offV + kc * 16 * ARB + np0 * 32);
        ldsm4t(vh1, vbse + offV + kc * 16 * ARB + np1 * 32);
        ldsm4t(vl1, vbse + APL + offV + kc * 16 * ARB + np1 * 32);
        mma_bf16(oacc[2 * np0],     pah, vh0);
        mma_bf16(oacc[2 * np0 + 1], pah, vh0 + 2);
        mma_bf16(oacc[2 * np1],     pah, vh1);
        mma_bf16(oacc[2 * np1 + 1], pah, vh1 + 2);
        mma_bf16(oacc[2 * np0],     pah, vl0);
        mma_bf16(oacc[2 * np0 + 1], pah, vl0 + 2);
        mma_bf16(oacc[2 * np1],     pah, vl1);
        mma_bf16(oacc[2 * np1 + 1], pah, vl1 + 2);
        mma_bf16(oacc[2 * np0],     pal, vh0);
        mma_bf16(oacc[2 * np0 + 1], pal, vh0 + 2);
        mma_bf16(oacc[2 * np1],     pal, vh1);
        mma_bf16(oacc[2 * np1 + 1], pal, vh1 + 2);
      }
      {
        uint32_t vh[4], vl[4];
        ldsm4t(vh, vbse + offV + kc * 16 * ARB + 4 * 32);
        ldsm4t(vl, vbse + APL + offV + kc * 16 * ARB + 4 * 32);
        mma_bf16(oacc[8], pah, vh);
        mma_bf16(oacc[8], pah, vl);
        mma_bf16(oacc[8], pal, vh);
      }
    }
    __syncthreads();
  }

  float inv0 = 1.f / ls0, inv1 = 1.f / ls1;
  int r0 = m0 + warp * 16 + g, r1 = r0 + 8;
  size_t base0 = ((size_t)b * Ntok + r0) * Hdim + h * HeadD;
  size_t base1 = ((size_t)b * Ntok + r1) * Hdim + h * HeadD;
#pragma unroll
  for (int nt = 0; nt < 9; nt++) {
    int col = nt * 8 + 2 * tg;
    float v0 = oacc[nt][0] * inv0, v1 = oacc[nt][1] * inv0;
    float v2 = oacc[nt][2] * inv1, v3 = oacc[nt][3] * inv1;
    bf16 h0, l0, h1, l1, h2, l2, h3, l3;
    split_bf16(v0, h0, l0); split_bf16(v1, h1, l1);
    split_bf16(v2, h2, l2); split_bf16(v3, h3, l3);
    *(bf162*)(Oh + base0 + col) = __halves2bfloat162(h0, h1);
    *(bf162*)(Ol + base0 + col) = __halves2bfloat162(l0, l1);
    *(bf162*)(Oh + base1 + col) = __halves2bfloat162(h2, h3);
    *(bf162*)(Ol + base1 + col) = __halves2bfloat162(l2, l3);
  }
}

// ------------------------------ launcher -----------------------------------
static float* sym_f(const void* s) { void* p; cudaGetSymbolAddress(&p, s); return (float*)p; }
static bf16*  sym_b(const void* s) { void* p; cudaGetSymbolAddress(&p, s); return (bf16*)p; }

extern "C" void kernel_launch(void* const* d_in, const int* in_sizes, int n_in,
                              void* d_out, int out_size) {
  (void)in_sizes; (void)n_in; (void)out_size;
  const float* x        = (const float*)d_in[0];
  const float* c        = (const float*)d_in[1];
  const float* t_emb    = (const float*)d_in[2];
  const float* qkv_w    = (const float*)d_in[3];
  const float* qkv_b    = (const float*)d_in[4];
  const float* proj_w   = (const float*)d_in[5];
  const float* proj_b   = (const float*)d_in[6];
  const float* to_q_w   = (const float*)d_in[7];
  const float* to_k_w   = (const float*)d_in[8];
  const float* to_v_w   = (const float*)d_in[9];
  const float* to_out_w = (const float*)d_in[10];
  const float* to_out_b = (const float*)d_in[11];
  const float* mlp_w1   = (const float*)d_in[12];
  const float* mlp_b1   = (const float*)d_in[13];
  const float* mlp_w2   = (const float*)d_in[14];
  const float* mlp_b2   = (const float*)d_in[15];
  const float* ada_w    = (const float*)d_in[16];
  const float* ada_b    = (const float*)d_in[17];
  float* out = (float*)d_out;

  float *mod = sym_f(&g_mod), *xb = sym_f(&g_xb);
  bf16 *lnh = sym_b(&g_ln_h), *lnl = sym_b(&g_ln_l);
  bf16 *ath = sym_b(&g_at_h), *atl = sym_b(&g_at_l);
  bf16 *xbh = sym_b(&g_xb_h), *xbl = sym_b(&g_xb_l);
  bf16 *qkh = sym_b(&g_qkv_h), *qkl = sym_b(&g_qkv_l);
  bf16 *kvh = sym_b(&g_kv_h), *kvl = sym_b(&g_kv_l);
  bf16 *hdh = sym_b(&g_hid_h), *hdl = sym_b(&g_hid_l);
  bf16 *ch = sym_b(&g_c_h), *cl = sym_b(&g_c_l);
  bf16 *wqkvh = sym_b(&g_wqkv_h), *wqkvl = sym_b(&g_wqkv_l);
  bf16 *wprh = sym_b(&g_wpr_h), *wprl = sym_b(&g_wpr_l);
  bf16 *wqh = sym_b(&g_wq_h), *wql = sym_b(&g_wq_l);
  bf16 *wkvh = sym_b(&g_wkv_h), *wkvl = sym_b(&g_wkv_l);
  bf16 *woh = sym_b(&g_wo_h), *wol = sym_b(&g_wo_l);
  bf16 *w1h = sym_b(&g_w1_h), *w1l = sym_b(&g_w1_l);
  bf16 *w2h = sym_b(&g_w2_h), *w2l = sym_b(&g_w2_l);

  cudaFuncSetAttribute(attn_tc,
                       cudaFuncAttributeMaxDynamicSharedMemorySize, ATSM);
#define SETSM(k) cudaFuncSetAttribute(k, \
    cudaFuncAttributeMaxDynamicSharedMemorySize, GSMEM)
  SETSM((gemm_tc<EPI_BIAS, false, true>));
  SETSM((gemm_tc<EPI_GELU, false, true>));
  SETSM((gemm_tc<EPI_RESGATE, true, true>));
  SETSM((gemm_tc<EPI_RESGATE, true, false>));
#undef SETSM

  const float sl2e = (1.f / sqrtf((float)HeadD)) * 1.4426950408889634f;

  // fused conversions (to_k and to_v written into one concatenated buffer)
  {
    CvtJobs J;
    const float* s[9] = {qkv_w, proj_w, to_q_w, to_k_w, to_v_w,
                         to_out_w, mlp_w1, mlp_w2, c};
    bf16* hh[9] = {wqkvh, wprh, wqh, wkvh, wkvh + Hdim * CtxD,
                   woh, w1h, w2h, ch};
    bf16* ll[9] = {wqkvl, wprl, wql, wkvl, wkvl + Hdim * CtxD,
                   wol, w1l, w2l, cl};
    int nn[9] = {3 * Hdim * Hdim, Hdim * Hdim, Hdim * Hdim, Hdim * CtxD,
                 Hdim * CtxD, Hdim * Hdim, MlpD * Hdim, Hdim * MlpD,
                 Crows * CtxD};
    for (int i = 0; i < 9; i++) { J.src[i] = s[i]; J.hi[i] = hh[i];
                                  J.lo[i] = ll[i]; J.n[i] = nn[i]; }
    dim3 g((MlpD * Hdim / 4 + 255) / 256, 9);
    cvt_all_kernel<<<g, 256>>>(J);
  }
  ada_kernel<<<ModW / 128, 128>>>(t_emb, ada_w, ada_b, mod);
  ln_mod_kernel<<<Mrows, 256>>>(x, mod, 0, 1, lnh, lnl);
  // qkv
  {
    dim3 g(3 * Hdim / 128, Mrows / 64);
    gemm_tc<EPI_BIAS, false, true><<<g, 128, GSMEM>>>(
        lnh, lnl, wqkvh, wqkvl, qkv_b, nullptr, nullptr,
        nullptr, qkh, qkl, Mrows, 3 * Hdim, Hdim);
  }
  // self-attention
  {
    dim3 g(Ntok / 128, NHead, Bsz);
    attn_tc<<<g, 256, ATSM>>>(
        qkh, qkl, (long long)Ntok * 3 * Hdim, 3 * Hdim,
        qkh + Hdim, qkl + Hdim, qkh + 2 * Hdim, qkl + 2 * Hdim,
        (long long)Ntok * 3 * Hdim, 3 * Hdim,
        ath, atl, Ntok, sl2e);
  }
  // proj + gated residual; cross-attn Q
  {
    dim3 g(Hdim / 128, Mrows / 64);
    gemm_tc<EPI_RESGATE, true, true><<<g, 128, GSMEM>>>(
        ath, atl, wprh, wprl, proj_b, x, mod + 2 * Hdim,
        xb, xbh, xbl, Mrows, Hdim, Hdim);
    gemm_tc<EPI_BIAS, false, true><<<g, 128, GSMEM>>>(
        xbh, xbl, wqh, wql, nullptr, nullptr, nullptr,
        nullptr, lnh, lnl, Mrows, Hdim, Hdim);
  }
  // cross-attn K|V (merged, one GEMM)
  {
    dim3 g(KVW / 128, (Crows + 63) / 64);
    gemm_tc<EPI_BIAS, false, true><<<g, 128, GSMEM>>>(
        ch, cl, wkvh, wkvl, nullptr, nullptr, nullptr,
        nullptr, kvh, kvl, Crows, KVW, CtxD);
  }
  // cross-attention (K at col 0, V at col Hdim, row stride KVW)
  {
    dim3 g(Ntok / 128, NHead, Bsz);
    attn_tc<<<g, 256, ATSM>>>(
        lnh, lnl, (long long)Ntok * Hdim, Hdim,
        kvh, kvl, kvh + Hdim, kvl + Hdim, (long long)CtxT * KVW, KVW,
        ath, atl, CtxT, sl2e);
  }
  // to_out + residual
  {
    dim3 g(Hdim / 128, Mrows / 64);
    gemm_tc<EPI_RESGATE, true, false><<<g, 128, GSMEM>>>(
        ath, atl, woh, wol, to_out_b, xb, nullptr,
        xb, nullptr, nullptr, Mrows, Hdim, Hdim);
  }
  ln_mod_kernel<<<Mrows, 256>>>(xb, mod, 3, 4, lnh, lnl);
  // MLP
  {
    dim3 g1(MlpD / 128, Mrows / 64);
    gemm_tc<EPI_GELU, false, true><<<g1, 128, GSMEM>>>(
        lnh, lnl, w1h, w1l, mlp_b1, nullptr, nullptr,
        nullptr, hdh, hdl, Mrows, MlpD, Hdim);
    dim3 g2(Hdim / 128, Mrows / 64);
    gemm_tc<EPI_RESGATE, true, false><<<g2, 128, GSMEM>>>(
        hdh, hdl, w2h, w2l, mlp_b2, xb, mod + 5 * Hdim,
        out, nullptr, nullptr, Mrows, Hdim, MlpD);
  }
}

// round 8
// speedup vs baseline: 2.3751x; 2.3751x over previous
#include <cuda_runtime.h>
#include <cuda_fp16.h>
#include <math.h>
#include <stdint.h>

// ---------------------------------------------------------------------------
// DiT block. Round 8: fp16 GEMMs with single-sided truncation:
// activations single fp16, weights fp16 hi/lo (2 MMAs/tile); attention all
// single fp16 (1 MMA/term). K-tile 64, 128x128 tiles, 256 thr, 2 CTAs/SM.
// ---------------------------------------------------------------------------

#define Bsz   8
#define Ntok  1024
#define Hdim  1152
#define NHead 16
#define HeadD 72
#define CtxD  768
#define CtxT  77
#define MlpD  4608
#define Mrows (Bsz * Ntok)     // 8192
#define Crows (Bsz * CtxT)     // 616
#define ModW  (6 * Hdim)       // 6912
#define KVW   (2 * Hdim)       // 2304

typedef __half  f16;
typedef __half2 f162;

// ------------------------- scratch (no allocations) ------------------------
__device__ float g_mod [Bsz * ModW];
__device__ float g_xb  [Mrows * Hdim];

__device__ f16 g_ln  [Mrows * Hdim];        // ln out / xattn Q
__device__ f16 g_at  [Mrows * Hdim];        // attn out
__device__ f16 g_xbh [Mrows * Hdim];        // fp16 copy of xb
__device__ f16 g_qkv [Mrows * 3 * Hdim];
__device__ f16 g_kv  [Crows * KVW];
__device__ f16 g_hid [Mrows * MlpD];
__device__ f16 g_c   [Crows * CtxD];
__device__ f16 g_wqkv_h[3 * Hdim * Hdim], g_wqkv_l[3 * Hdim * Hdim];
__device__ f16 g_wpr_h [Hdim * Hdim],     g_wpr_l [Hdim * Hdim];
__device__ f16 g_wq_h  [Hdim * Hdim],     g_wq_l  [Hdim * Hdim];
__device__ f16 g_wkv_h [KVW * CtxD],      g_wkv_l [KVW * CtxD];
__device__ f16 g_wo_h  [Hdim * Hdim],     g_wo_l  [Hdim * Hdim];
__device__ f16 g_w1_h  [MlpD * Hdim],     g_w1_l  [MlpD * Hdim];
__device__ f16 g_w2_h  [Hdim * MlpD],     g_w2_l  [Hdim * MlpD];

// ------------------------------ helpers ------------------------------------
__device__ __forceinline__ void split_f16(float v, f16& h, f16& l) {
  h = __float2half(v);
  l = __float2half(v - __half2float(h));
}
__device__ __forceinline__ float ex2(float x) {
  float y; asm("ex2.approx.f32 %0, %1;" : "=f"(y) : "f"(x)); return y;
}
__device__ __forceinline__ uint32_t pack_f16x2(float lo, float hi) {
  uint32_t d;
  asm("cvt.rn.f16x2.f32 %0, %1, %2;" : "=r"(d) : "f"(hi), "f"(lo));
  return d;
}

// -------------------- fused weight/context conversion ----------------------
struct CvtJobs {
  const float* src[9];
  f16* hi[9];
  f16* lo[9];   // nullptr => single-precision-plane job
  int n[9];
};

__global__ __launch_bounds__(256) void cvt_all_kernel(CvtJobs J) {
  int t = blockIdx.y;
  int i = (blockIdx.x * 256 + threadIdx.x) * 4;
  if (i >= J.n[t]) return;
  float4 v = *(const float4*)(J.src[t] + i);
  f16* hi = J.hi[t];
  f16* lo = J.lo[t];
  if (lo) {
    f16 h0, l0, h1, l1, h2, l2, h3, l3;
    split_f16(v.x, h0, l0); split_f16(v.y, h1, l1);
    split_f16(v.z, h2, l2); split_f16(v.w, h3, l3);
    *(f162*)(hi + i)     = __halves2half2(h0, h1);
    *(f162*)(hi + i + 2) = __halves2half2(h2, h3);
    *(f162*)(lo + i)     = __halves2half2(l0, l1);
    *(f162*)(lo + i + 2) = __halves2half2(l2, l3);
  } else {
    *(f162*)(hi + i)     = __floats2half2_rn(v.x, v.y);
    *(f162*)(hi + i + 2) = __floats2half2_rn(v.z, v.w);
  }
}

// --------------------------- adaLN modulation ------------------------------
__global__ __launch_bounds__(128) void ada_kernel(
    const float* __restrict__ t_emb, const float* __restrict__ ada_w,
    const float* __restrict__ ada_b, float* __restrict__ mod) {
  __shared__ float se[Bsz * Hdim];
  int tid = threadIdx.x;
  for (int i = tid; i < Bsz * Hdim; i += 128) {
    float v = t_emb[i];
    se[i] = v / (1.f + __expf(-v));
  }
  __syncthreads();
  int j = blockIdx.x * 128 + tid;
  const float* w = ada_w + (size_t)j * Hdim;
  float acc[Bsz];
#pragma unroll
  for (int b = 0; b < Bsz; b++) acc[b] = 0.f;
  for (int k = 0; k < Hdim; k += 4) {
    float4 wv = *(const float4*)(w + k);
#pragma unroll
    for (int b = 0; b < Bsz; b++) {
      const float* s = se + b * Hdim + k;
      acc[b] += wv.x * s[0] + wv.y * s[1] + wv.z * s[2] + wv.w * s[3];
    }
  }
  float bb = ada_b[j];
#pragma unroll
  for (int b = 0; b < Bsz; b++) mod[b * ModW + j] = acc[b] + bb;
}

// ----------------- LayerNorm + modulate -> fp16 -----------------------------
__global__ __launch_bounds__(256) void ln_mod_kernel(
    const float* __restrict__ x, const float* __restrict__ mod,
    int sh_off, int sc_off, f16* __restrict__ o16) {
  int row = blockIdx.x;
  int b = row >> 10;
  const float* xr = x + (size_t)row * Hdim;
  int tid = threadIdx.x;
  float s = 0.f, ss = 0.f;
  for (int i = tid; i < Hdim; i += 256) {
    float v = xr[i];
    s += v; ss += v * v;
  }
#pragma unroll
  for (int o = 16; o > 0; o >>= 1) {
    s  += __shfl_xor_sync(0xffffffffu, s, o);
    ss += __shfl_xor_sync(0xffffffffu, ss, o);
  }
  __shared__ float rs[8], rss[8], stat[2];
  int w = tid >> 5;
  if ((tid & 31) == 0) { rs[w] = s; rss[w] = ss; }
  __syncthreads();
  if (tid == 0) {
    float S = 0.f, SS = 0.f;
#pragma unroll
    for (int i = 0; i < 8; i++) { S += rs[i]; SS += rss[i]; }
    float mu = S * (1.f / Hdim);
    float var = SS * (1.f / Hdim) - mu * mu;
    stat[0] = mu;
    stat[1] = rsqrtf(var + 1e-6f);
  }
  __syncthreads();
  float mu = stat[0], rstd = stat[1];
  const float* sh = mod + b * ModW + sh_off * Hdim;
  const float* sc = mod + b * ModW + sc_off * Hdim;
  f16* o = o16 + (size_t)row * Hdim;
  for (int i = tid; i < Hdim; i += 256)
    o[i] = __float2half((xr[i] - mu) * rstd * (1.f + sc[i]) + sh[i]);
}

// ------------------- tensor-core GEMM (NT, fp16 x2) -------------------------
__device__ __forceinline__ float gelu_tanh(float v) {
  const float c = 0.7978845608028654f;
  return 0.5f * v * (1.f + tanhf(c * (v + 0.044715f * v * v * v)));
}

#define EPI_BIAS    0
#define EPI_GELU    1
#define EPI_RESGATE 2

__device__ __forceinline__ void mma_f16(float c[4], const uint32_t a[4],
                                        const uint32_t b[2]) {
  asm volatile(
      "mma.sync.aligned.m16n8k16.row.col.f32.f16.f16.f32 "
      "{%0,%1,%2,%3}, {%4,%5,%6,%7}, {%8,%9}, {%0,%1,%2,%3};"
      : "+f"(c[0]), "+f"(c[1]), "+f"(c[2]), "+f"(c[3])
      : "r"(a[0]), "r"(a[1]), "r"(a[2]), "r"(a[3]), "r"(b[0]), "r"(b[1]));
}

__device__ __forceinline__ void ldsm4(uint32_t r[4], uint32_t addr) {
  asm volatile("ldmatrix.sync.aligned.m8n8.x4.shared.b16 {%0,%1,%2,%3}, [%4];"
               : "=r"(r[0]), "=r"(r[1]), "=r"(r[2]), "=r"(r[3]) : "r"(addr));
}
__device__ __forceinline__ void ldsm4t(uint32_t r[4], uint32_t addr) {
  asm volatile(
      "ldmatrix.sync.aligned.m8n8.x4.trans.shared.b16 {%0,%1,%2,%3}, [%4];"
      : "=r"(r[0]), "=r"(r[1]), "=r"(r[2]), "=r"(r[3]) : "r"(addr));
}

__device__ __forceinline__ void cp16(uint32_t dst, const void* src, bool p) {
  int sz = p ? 16 : 0;
  asm volatile("cp.async.cg.shared.global [%0], [%1], 16, %2;\n"
               :: "r"(dst), "l"(src), "r"(sz));
}

// K-tile 64: plane = 128 rows x 144B (128B data + 16B pad; 9 slots coprime 8).
#define PL_B    18432
#define STAGE_B (3 * PL_B)       // A, Bh, Bl = 55296
#define GSMEM   (2 * STAGE_B)    // 110592

template <int EPI, bool OUTF, bool OUTB>
__global__ __launch_bounds__(256, 2) void gemm_tc(
    const f16* __restrict__ A,
    const f16* __restrict__ Wh, const f16* __restrict__ Wl,
    const float* __restrict__ bias, const float* __restrict__ res,
    const float* __restrict__ gate, float* __restrict__ C,
    f16* __restrict__ C16,
    int M, int N, int K) {
  extern __shared__ char smc[];
  uint32_t sbase = (uint32_t)__cvta_generic_to_shared(smc);
  int tid = threadIdx.x;
  int warp = tid >> 5, lane = tid & 31;
  int wm = warp & 3, wn = warp >> 2;     // 4 warps M x 2 warps N
  int m0 = blockIdx.y << 7, n0 = blockIdx.x << 7;

  float acc[2][8][4];
#pragma unroll
  for (int mt = 0; mt < 2; mt++)
#pragma unroll
    for (int nt = 0; nt < 8; nt++)
#pragma unroll
      for (int f = 0; f < 4; f++) acc[mt][nt][f] = 0.f;

  int lq = lane & 7, lb = (lane >> 3) & 1, lh = lane >> 4;
  uint32_t offA[2], offB[4];
#pragma unroll
  for (int mt = 0; mt < 2; mt++)
    offA[mt] = (uint32_t)((wm * 32 + mt * 16 + lq + lb * 8) * 144 + lh * 16);
#pragma unroll
  for (int j = 0; j < 4; j++)
    offB[j] = (uint32_t)(PL_B +
                         (wn * 64 + j * 16 + lq + lh * 8) * 144 + lb * 16);

  const int nk = K >> 6;

  // 3072 chunks/stage: A rows (1024) then Bh (1024) then Bl (1024).
  auto issue = [&](int kt, int s) {
    uint32_t st = sbase + s * STAGE_B;
    int k0 = kt << 6;
#pragma unroll
    for (int i = 0; i < 12; i++) {
      int idx = tid + (i << 8);
      int pl = idx >> 10;          // 0=A, 1=Bh, 2=Bl
      int cc = idx & 1023;
      int row = cc >> 3, ch = cc & 7;
      uint32_t d = st + pl * PL_B + row * 144 + ch * 16;
      const f16* src;
      bool ok = true;
      if (pl == 0) {
        int gm = m0 + row;
        ok = gm < M;
        src = A + (size_t)(ok ? gm : 0) * K + k0 + ch * 8;
      } else {
        src = (pl == 2 ? Wl : Wh) + (size_t)(n0 + row) * K + k0 + ch * 8;
      }
      cp16(d, src, ok);
    }
    asm volatile("cp.async.commit_group;\n");
  };

  issue(0, 0);
  for (int kt = 0; kt < nk; kt++) {
    int s = kt & 1;
    if (kt + 1 < nk) {
      issue(kt + 1, s ^ 1);
      asm volatile("cp.async.wait_group 1;\n");
    } else {
      asm volatile("cp.async.wait_group 0;\n");
    }
    __syncthreads();

    uint32_t sb = sbase + s * STAGE_B;
#pragma unroll
    for (int ks = 0; ks < 4; ks++) {
      uint32_t a_[2][4];
#pragma unroll
      for (int mt = 0; mt < 2; mt++)
        ldsm4(a_[mt], sb + offA[mt] + ks * 32);
#pragma unroll
      for (int jp = 0; jp < 2; jp++) {
        uint32_t bh0[4], bl0[4], bh1[4], bl1[4];
        ldsm4(bh0, sb + offB[2 * jp]     + ks * 32);
        ldsm4(bl0, sb + offB[2 * jp]     + PL_B + ks * 32);
        ldsm4(bh1, sb + offB[2 * jp + 1] + ks * 32);
        ldsm4(bl1, sb + offB[2 * jp + 1] + PL_B + ks * 32);
        float (*a0)[4] = acc[0], (*a1)[4] = acc[1];
        int q = 4 * jp;
        // term a*wh over 8 independent accumulators
        mma_f16(a0[q],     a_[0], bh0);
        mma_f16(a0[q + 1], a_[0], bh0 + 2);
        mma_f16(a1[q],     a_[1], bh0);
        mma_f16(a1[q + 1], a_[1], bh0 + 2);
        mma_f16(a0[q + 2], a_[0], bh1);
        mma_f16(a0[q + 3], a_[0], bh1 + 2);
        mma_f16(a1[q + 2], a_[1], bh1);
        mma_f16(a1[q + 3], a_[1], bh1 + 2);
        // term a*wl
        mma_f16(a0[q],     a_[0], bl0);
        mma_f16(a0[q + 1], a_[0], bl0 + 2);
        mma_f16(a1[q],     a_[1], bl0);
        mma_f16(a1[q + 1], a_[1], bl0 + 2);
        mma_f16(a0[q + 2], a_[0], bl1);
        mma_f16(a0[q + 3], a_[0], bl1 + 2);
        mma_f16(a1[q + 2], a_[1], bl1);
        mma_f16(a1[q + 3], a_[1], bl1 + 2);
      }
    }
    __syncthreads();
  }

  int g = lane >> 2, tg = lane & 3;
#pragma unroll
  for (int mt = 0; mt < 2; mt++) {
#pragma unroll
    for (int half = 0; half < 2; half++) {
      int m = m0 + wm * 32 + mt * 16 + g + half * 8;
      if (m >= M) continue;
      int bq = m >> 10;
#pragma unroll
      for (int nt = 0; nt < 8; nt++) {
        int n = n0 + wn * 64 + nt * 8 + tg * 2;
        float v0 = acc[mt][nt][half * 2 + 0];
        float v1 = acc[mt][nt][half * 2 + 1];
        if (bias) { v0 += bias[n]; v1 += bias[n + 1]; }
        if (EPI == EPI_GELU) { v0 = gelu_tanh(v0); v1 = gelu_tanh(v1); }
        if (EPI == EPI_RESGATE) {
          float g0 = 1.f, g1 = 1.f;
          if (gate) { g0 = gate[bq * ModW + n]; g1 = gate[bq * ModW + n + 1]; }
          v0 = res[(size_t)m * N + n] + g0 * v0;
          v1 = res[(size_t)m * N + n + 1] + g1 * v1;
        }
        if (OUTF)
          *(float2*)(C + (size_t)m * N + n) = make_float2(v0, v1);
        if (OUTB)
          *(f162*)(C16 + (size_t)m * N + n) = __floats2half2_rn(v0, v1);
      }
    }
  }
}

// ---------------- tensor-core flash attention (fp16 x1) ---------------------
#define ARB   176
#define APL   (128 * ARB)
#define ATSM  (5 * APL)            // Q + 2 stages x (K,V) = 112640

__global__ __launch_bounds__(256) void attn_tc(
    const f16* __restrict__ Q, long long qbs, int ldq,
    const f16* __restrict__ Kp, const f16* __restrict__ Vp,
    long long kbs, int ldk,
    f16* __restrict__ O,
    int kv_len, float sl2e) {
  extern __shared__ char smb[];
  uint32_t sb = (uint32_t)__cvta_generic_to_shared(smb);
  int b = blockIdx.z, h = blockIdx.y;
  int m0 = blockIdx.x * 128;
  int tid = threadIdx.x, warp = tid >> 5, lane = tid & 31;
  int g = lane >> 2, tg = lane & 3;
  int lq = lane & 7, lb = (lane >> 3) & 1, lh = lane >> 4;

  const f16* Qb = Q  + (size_t)b * qbs + (size_t)m0 * ldq + h * HeadD;
  const f16* Kb = Kp + (size_t)b * kbs + h * HeadD;
  const f16* Vb = Vp + (size_t)b * kbs + h * HeadD;

  // zero hd-padding (cols 72..87) of all 5 planes
  for (int i = tid; i < 640; i += 256) {
    int p = i >> 7, r = i & 127;
    uint32_t ad = sb + p * APL + r * ARB + 144;
    asm volatile("st.shared.v4.b32 [%0], {%1,%1,%1,%1};" :: "r"(ad), "r"(0));
    asm volatile("st.shared.v4.b32 [%0], {%1,%1,%1,%1};"
                 :: "r"(ad + 16), "r"(0));
  }

  // Q: 128 rows x 9 chunks
  for (int i = tid; i < 1152; i += 256) {
    int r = i / 9, ch = i % 9;
    cp16(sb + r * ARB + ch * 16, Qb + (size_t)r * ldq + ch * 8, true);
  }

  auto loadKV = [&](int j0, int s) {
    uint32_t st = sb + APL + s * 2 * APL;
    for (int i = tid; i < 1152; i += 256) {
      int r = i / 9, ch = i % 9;
      bool ok = (j0 + r) < kv_len;
      int rc = ok ? (j0 + r) : 0;
      size_t off = (size_t)rc * ldk + ch * 8;
      uint32_t d = st + r * ARB + ch * 16;
      cp16(d,       Kb + off, ok);
      cp16(d + APL, Vb + off, ok);
    }
    asm volatile("cp.async.commit_group;\n");
  };

  int iters = (kv_len + 127) >> 7;
  loadKV(0, 0);
  if (iters > 1) loadKV(128, 1);

  float m0r = -1e30f, m1r = -1e30f, ls0 = 0.f, ls1 = 0.f;
  float oacc[9][4];
#pragma unroll
  for (int nt = 0; nt < 9; nt++)
#pragma unroll
    for (int f = 0; f < 4; f++) oacc[nt][f] = 0.f;

  uint32_t offA = (uint32_t)((warp * 16 + lq + lb * 8) * ARB + lh * 16);
  uint32_t offB = (uint32_t)((lq + lh * 8) * ARB + lb * 16);
  uint32_t offV = (uint32_t)((lq + lb * 8) * ARB + lh * 16);

  for (int it = 0; it < iters; it++) {
    if (it + 1 < iters) {
      if (it > 0) loadKV((it + 1) * 128, (it + 1) & 1);
      asm volatile("cp.async.wait_group 1;\n");
    } else {
      asm volatile("cp.async.wait_group 0;\n");
    }
    __syncthreads();

    uint32_t kbse = sb + APL + (it & 1) * 2 * APL;

    float sa[16][4];
#pragma unroll
    for (int j = 0; j < 16; j++)
#pragma unroll
      for (int f = 0; f < 4; f++) sa[j][f] = 0.f;

#pragma unroll
    for (int ks = 0; ks < 5; ks++) {
      uint32_t a_[4];
      ldsm4(a_, sb + offA + ks * 32);
#pragma unroll
      for (int ntp = 0; ntp < 4; ntp++) {
        uint32_t b0[4], b1[4];
        ldsm4(b0, kbse + offB + (2 * ntp) * 16 * ARB + ks * 32);
        ldsm4(b1, kbse + offB + (2 * ntp + 1) * 16 * ARB + ks * 32);
        int q = 4 * ntp;
        mma_f16(sa[q],     a_, b0);
        mma_f16(sa[q + 1], a_, b0 + 2);
        mma_f16(sa[q + 2], a_, b1);
        mma_f16(sa[q + 3], a_, b1 + 2);
      }
    }

    int j0 = it * 128;
    bool msk = (j0 + 128) > kv_len;
    float mx0 = -1e30f, mx1 = -1e30f;
#pragma unroll
    for (int j = 0; j < 16; j++) {
#pragma unroll
      for (int e = 0; e < 4; e++) {
        float v = sa[j][e] * sl2e;
        if (msk) {
          int col = j * 8 + 2 * tg + (e & 1);
          if (j0 + col >= kv_len) v = -1e30f;
        }
        sa[j][e] = v;
      }
      mx0 = fmaxf(mx0, fmaxf(sa[j][0], sa[j][1]));
      mx1 = fmaxf(mx1, fmaxf(sa[j][2], sa[j][3]));
    }
    mx0 = fmaxf(mx0, __shfl_xor_sync(0xffffffffu, mx0, 1));
    mx0 = fmaxf(mx0, __shfl_xor_sync(0xffffffffu, mx0, 2));
    mx1 = fmaxf(mx1, __shfl_xor_sync(0xffffffffu, mx1, 1));
    mx1 = fmaxf(mx1, __shfl_xor_sync(0xffffffffu, mx1, 2));
    float mn0 = fmaxf(m0r, mx0), mn1 = fmaxf(m1r, mx1);
    float al0 = ex2(m0r - mn0), al1 = ex2(m1r - mn1);
    m0r = mn0; m1r = mn1;

    float s0 = 0.f, s1 = 0.f;
#pragma unroll
    for (int j = 0; j < 16; j++) {
      float p0 = ex2(sa[j][0] - mn0), p1 = ex2(sa[j][1] - mn0);
      float p2 = ex2(sa[j][2] - mn1), p3 = ex2(sa[j][3] - mn1);
      sa[j][0] = p0; sa[j][1] = p1; sa[j][2] = p2; sa[j][3] = p3;
      s0 += p0 + p1; s1 += p2 + p3;
    }
    s0 += __shfl_xor_sync(0xffffffffu, s0, 1);
    s0 += __shfl_xor_sync(0xffffffffu, s0, 2);
    s1 += __shfl_xor_sync(0xffffffffu, s1, 1);
    s1 += __shfl_xor_sync(0xffffffffu, s1, 2);
    ls0 = ls0 * al0 + s0;
    ls1 = ls1 * al1 + s1;
#pragma unroll
    for (int nt = 0; nt < 9; nt++) {
      oacc[nt][0] *= al0; oacc[nt][1] *= al0;
      oacc[nt][2] *= al1; oacc[nt][3] *= al1;
    }

    uint32_t vbse = kbse + APL;
#pragma unroll
    for (int kc = 0; kc < 8; kc++) {
      uint32_t pa[4];
#pragma unroll
      for (int jj = 0; jj < 2; jj++) {
        int j = 2 * kc + jj;
        pa[2 * jj]     = pack_f16x2(sa[j][0], sa[j][1]);
        pa[2 * jj + 1] = pack_f16x2(sa[j][2], sa[j][3]);
      }
#pragma unroll
      for (int npp = 0; npp < 2; npp++) {
        int np0 = 2 * npp, np1 = 2 * npp + 1;
        uint32_t v0[4], v1[4];
        ldsm4t(v0, vbse + offV + kc * 16 * ARB + np0 * 32);
        ldsm4t(v1, vbse + offV + kc * 16 * ARB + np1 * 32);
        mma_f16(oacc[2 * np0],     pa, v0);
        mma_f16(oacc[2 * np0 + 1], pa, v0 + 2);
        mma_f16(oacc[2 * np1],     pa, v1);
        mma_f16(oacc[2 * np1 + 1], pa, v1 + 2);
      }
      {
        uint32_t v4[4];
        ldsm4t(v4, vbse + offV + kc * 16 * ARB + 4 * 32);
        mma_f16(oacc[8], pa, v4);
      }
    }
    __syncthreads();
  }

  float inv0 = 1.f / ls0, inv1 = 1.f / ls1;
  int r0 = m0 + warp * 16 + g, r1 = r0 + 8;
  size_t base0 = ((size_t)b * Ntok + r0) * Hdim + h * HeadD;
  size_t base1 = ((size_t)b * Ntok + r1) * Hdim + h * HeadD;
#pragma unroll
  for (int nt = 0; nt < 9; nt++) {
    int col = nt * 8 + 2 * tg;
    *(f162*)(O + base0 + col) =
        __floats2half2_rn(oacc[nt][0] * inv0, oacc[nt][1] * inv0);
    *(f162*)(O + base1 + col) =
        __floats2half2_rn(oacc[nt][2] * inv1, oacc[nt][3] * inv1);
  }
}

// ------------------------------ launcher -----------------------------------
static float* sym_f(const void* s) { void* p; cudaGetSymbolAddress(&p, s); return (float*)p; }
static f16*   sym_h(const void* s) { void* p; cudaGetSymbolAddress(&p, s); return (f16*)p; }

extern "C" void kernel_launch(void* const* d_in, const int* in_sizes, int n_in,
                              void* d_out, int out_size) {
  (void)in_sizes; (void)n_in; (void)out_size;
  const float* x        = (const float*)d_in[0];
  const float* c        = (const float*)d_in[1];
  const float* t_emb    = (const float*)d_in[2];
  const float* qkv_w    = (const float*)d_in[3];
  const float* qkv_b    = (const float*)d_in[4];
  const float* proj_w   = (const float*)d_in[5];
  const float* proj_b   = (const float*)d_in[6];
  const float* to_q_w   = (const float*)d_in[7];
  const float* to_k_w   = (const float*)d_in[8];
  const float* to_v_w   = (const float*)d_in[9];
  const float* to_out_w = (const float*)d_in[10];
  const float* to_out_b = (const float*)d_in[11];
  const float* mlp_w1   = (const float*)d_in[12];
  const float* mlp_b1   = (const float*)d_in[13];
  const float* mlp_w2   = (const float*)d_in[14];
  const float* mlp_b2   = (const float*)d_in[15];
  const float* ada_w    = (const float*)d_in[16];
  const float* ada_b    = (const float*)d_in[17];
  float* out = (float*)d_out;

  float *mod = sym_f(&g_mod), *xb = sym_f(&g_xb);
  f16 *ln = sym_h(&g_ln), *at = sym_h(&g_at), *xbh = sym_h(&g_xbh);
  f16 *qkv = sym_h(&g_qkv), *kv = sym_h(&g_kv), *hid = sym_h(&g_hid);
  f16 *cc = sym_h(&g_c);
  f16 *wqkvh = sym_h(&g_wqkv_h), *wqkvl = sym_h(&g_wqkv_l);
  f16 *wprh = sym_h(&g_wpr_h), *wprl = sym_h(&g_wpr_l);
  f16 *wqh = sym_h(&g_wq_h), *wql = sym_h(&g_wq_l);
  f16 *wkvh = sym_h(&g_wkv_h), *wkvl = sym_h(&g_wkv_l);
  f16 *woh = sym_h(&g_wo_h), *wol = sym_h(&g_wo_l);
  f16 *w1h = sym_h(&g_w1_h), *w1l = sym_h(&g_w1_l);
  f16 *w2h = sym_h(&g_w2_h), *w2l = sym_h(&g_w2_l);

  cudaFuncSetAttribute(attn_tc,
                       cudaFuncAttributeMaxDynamicSharedMemorySize, ATSM);
#define SETSM(k) cudaFuncSetAttribute(k, \
    cudaFuncAttributeMaxDynamicSharedMemorySize, GSMEM)
  SETSM((gemm_tc<EPI_BIAS, false, true>));
  SETSM((gemm_tc<EPI_GELU, false, true>));
  SETSM((gemm_tc<EPI_RESGATE, true, true>));
  SETSM((gemm_tc<EPI_RESGATE, true, false>));
#undef SETSM

  const float sl2e = (1.f / sqrtf((float)HeadD)) * 1.4426950408889634f;

  // conversions: 8 weight tensors (hi/lo) + context (single)
  {
    CvtJobs J;
    const float* s[9] = {qkv_w, proj_w, to_q_w, to_k_w, to_v_w,
                         to_out_w, mlp_w1, mlp_w2, c};
    f16* hh[9] = {wqkvh, wprh, wqh, wkvh, wkvh + Hdim * CtxD,
                  woh, w1h, w2h, cc};
    f16* ll[9] = {wqkvl, wprl, wql, wkvl, wkvl + Hdim * CtxD,
                  wol, w1l, w2l, nullptr};
    int nn[9] = {3 * Hdim * Hdim, Hdim * Hdim, Hdim * Hdim, Hdim * CtxD,
                 Hdim * CtxD, Hdim * Hdim, MlpD * Hdim, Hdim * MlpD,
                 Crows * CtxD};
    for (int i = 0; i < 9; i++) { J.src[i] = s[i]; J.hi[i] = hh[i];
                                  J.lo[i] = ll[i]; J.n[i] = nn[i]; }
    dim3 g((MlpD * Hdim / 4 + 255) / 256, 9);
    cvt_all_kernel<<<g, 256>>>(J);
  }
  ada_kernel<<<ModW / 128, 128>>>(t_emb, ada_w, ada_b, mod);
  ln_mod_kernel<<<Mrows, 256>>>(x, mod, 0, 1, ln);
  // qkv
  {
    dim3 g(3 * Hdim / 128, Mrows / 128);
    gemm_tc<EPI_BIAS, false, true><<<g, 256, GSMEM>>>(
        ln, wqkvh, wqkvl, qkv_b, nullptr, nullptr,
        nullptr, qkv, Mrows, 3 * Hdim, Hdim);
  }
  // self-attention
  {
    dim3 g(Ntok / 128, NHead, Bsz);
    attn_tc<<<g, 256, ATSM>>>(
        qkv, (long long)Ntok * 3 * Hdim, 3 * Hdim,
        qkv + Hdim, qkv + 2 * Hdim, (long long)Ntok * 3 * Hdim, 3 * Hdim,
        at, Ntok, sl2e);
  }
  // proj + gated residual; cross-attn Q
  {
    dim3 g(Hdim / 128, Mrows / 128);
    gemm_tc<EPI_RESGATE, true, true><<<g, 256, GSMEM>>>(
        at, wprh, wprl, proj_b, x, mod + 2 * Hdim,
        xb, xbh, Mrows, Hdim, Hdim);
    gemm_tc<EPI_BIAS, false, true><<<g, 256, GSMEM>>>(
        xbh, wqh, wql, nullptr, nullptr, nullptr,
        nullptr, ln, Mrows, Hdim, Hdim);
  }
  // cross-attn K|V (merged)
  {
    dim3 g(KVW / 128, (Crows + 127) / 128);
    gemm_tc<EPI_BIAS, false, true><<<g, 256, GSMEM>>>(
        cc, wkvh, wkvl, nullptr, nullptr, nullptr,
        nullptr, kv, Crows, KVW, CtxD);
  }
  // cross-attention
  {
    dim3 g(Ntok / 128, NHead, Bsz);
    attn_tc<<<g, 256, ATSM>>>(
        ln, (long long)Ntok * Hdim, Hdim,
        kv, kv + Hdim, (long long)CtxT * KVW, KVW,
        at, CtxT, sl2e);
  }
  // to_out + residual
  {
    dim3 g(Hdim / 128, Mrows / 128);
    gemm_tc<EPI_RESGATE, true, false><<<g, 256, GSMEM>>>(
        at, woh, wol, to_out_b, xb, nullptr,
        xb, nullptr, Mrows, Hdim, Hdim);
  }
  ln_mod_kernel<<<Mrows, 256>>>(xb, mod, 3, 4, ln);
  // MLP
  {
    dim3 g1(MlpD / 128, Mrows / 128);
    gemm_tc<EPI_GELU, false, true><<<g1, 256, GSMEM>>>(
        ln, w1h, w1l, mlp_b1, nullptr, nullptr,
        nullptr, hid, Mrows, MlpD, Hdim);
    dim3 g2(Hdim / 128, Mrows / 128);
    gemm_tc<EPI_RESGATE, true, false><<<g2, 256, GSMEM>>>(
        hid, w2h, w2l, mlp_b2, xb, mod + 5 * Hdim,
        out, nullptr, Mrows, Hdim, MlpD);
  }
}

// round 9
// speedup vs baseline: 3.5245x; 1.4840x over previous
#include <cuda_runtime.h>
#include <cuda_fp16.h>
#include <math.h>
#include <stdint.h>

// ---------------------------------------------------------------------------
// DiT block. Round 9: single fp16 both sides (1 MMA per tile position) for
// all GEMMs + attention; fp32 accumulate. 128x128 tiles, K-tile 64, 2 CTA/SM.
// ---------------------------------------------------------------------------

#define Bsz   8
#define Ntok  1024
#define Hdim  1152
#define NHead 16
#define HeadD 72
#define CtxD  768
#define CtxT  77
#define MlpD  4608
#define Mrows (Bsz * Ntok)     // 8192
#define Crows (Bsz * CtxT)     // 616
#define ModW  (6 * Hdim)       // 6912
#define KVW   (2 * Hdim)       // 2304

typedef __half  f16;
typedef __half2 f162;

// ------------------------- scratch (no allocations) ------------------------
__device__ float g_mod [Bsz * ModW];
__device__ float g_xb  [Mrows * Hdim];

__device__ f16 g_ln  [Mrows * Hdim];
__device__ f16 g_at  [Mrows * Hdim];
__device__ f16 g_xbh [Mrows * Hdim];
__device__ f16 g_qkv [Mrows * 3 * Hdim];
__device__ f16 g_kv  [Crows * KVW];
__device__ f16 g_hid [Mrows * MlpD];
__device__ f16 g_c   [Crows * CtxD];
__device__ f16 g_wqkv[3 * Hdim * Hdim];
__device__ f16 g_wpr [Hdim * Hdim];
__device__ f16 g_wq  [Hdim * Hdim];
__device__ f16 g_wkv [KVW * CtxD];
__device__ f16 g_wo  [Hdim * Hdim];
__device__ f16 g_w1  [MlpD * Hdim];
__device__ f16 g_w2  [Hdim * MlpD];

// ------------------------------ helpers ------------------------------------
__device__ __forceinline__ float ex2(float x) {
  float y; asm("ex2.approx.f32 %0, %1;" : "=f"(y) : "f"(x)); return y;
}
__device__ __forceinline__ uint32_t pack_f16x2(float lo, float hi) {
  uint32_t d;
  asm("cvt.rn.f16x2.f32 %0, %1, %2;" : "=r"(d) : "f"(hi), "f"(lo));
  return d;
}

// -------------------- fused weight/context conversion ----------------------
struct CvtJobs {
  const float* src[9];
  f16* dst[9];
  int n[9];
};

__global__ __launch_bounds__(256) void cvt_all_kernel(CvtJobs J) {
  int t = blockIdx.y;
  int i = (blockIdx.x * 256 + threadIdx.x) * 4;
  if (i >= J.n[t]) return;
  float4 v = *(const float4*)(J.src[t] + i);
  f16* d = J.dst[t];
  *(f162*)(d + i)     = __floats2half2_rn(v.x, v.y);
  *(f162*)(d + i + 2) = __floats2half2_rn(v.z, v.w);
}

// --------------------------- adaLN modulation ------------------------------
__global__ __launch_bounds__(128) void ada_kernel(
    const float* __restrict__ t_emb, const float* __restrict__ ada_w,
    const float* __restrict__ ada_b, float* __restrict__ mod) {
  __shared__ float se[Bsz * Hdim];
  int tid = threadIdx.x;
  for (int i = tid; i < Bsz * Hdim; i += 128) {
    float v = t_emb[i];
    se[i] = v / (1.f + __expf(-v));
  }
  __syncthreads();
  int j = blockIdx.x * 128 + tid;
  const float* w = ada_w + (size_t)j * Hdim;
  float acc[Bsz];
#pragma unroll
  for (int b = 0; b < Bsz; b++) acc[b] = 0.f;
  for (int k = 0; k < Hdim; k += 4) {
    float4 wv = *(const float4*)(w + k);
#pragma unroll
    for (int b = 0; b < Bsz; b++) {
      const float* s = se + b * Hdim + k;
      acc[b] += wv.x * s[0] + wv.y * s[1] + wv.z * s[2] + wv.w * s[3];
    }
  }
  float bb = ada_b[j];
#pragma unroll
  for (int b = 0; b < Bsz; b++) mod[b * ModW + j] = acc[b] + bb;
}

// ----------------- LayerNorm + modulate -> fp16 -----------------------------
__global__ __launch_bounds__(256) void ln_mod_kernel(
    const float* __restrict__ x, const float* __restrict__ mod,
    int sh_off, int sc_off, f16* __restrict__ o16) {
  int row = blockIdx.x;
  int b = row >> 10;
  const float* xr = x + (size_t)row * Hdim;
  int tid = threadIdx.x;
  float s = 0.f, ss = 0.f;
  for (int i = tid; i < Hdim; i += 256) {
    float v = xr[i];
    s += v; ss += v * v;
  }
#pragma unroll
  for (int o = 16; o > 0; o >>= 1) {
    s  += __shfl_xor_sync(0xffffffffu, s, o);
    ss += __shfl_xor_sync(0xffffffffu, ss, o);
  }
  __shared__ float rs[8], rss[8], stat[2];
  int w = tid >> 5;
  if ((tid & 31) == 0) { rs[w] = s; rss[w] = ss; }
  __syncthreads();
  if (tid == 0) {
    float S = 0.f, SS = 0.f;
#pragma unroll
    for (int i = 0; i < 8; i++) { S += rs[i]; SS += rss[i]; }
    float mu = S * (1.f / Hdim);
    float var = SS * (1.f / Hdim) - mu * mu;
    stat[0] = mu;
    stat[1] = rsqrtf(var + 1e-6f);
  }
  __syncthreads();
  float mu = stat[0], rstd = stat[1];
  const float* sh = mod + b * ModW + sh_off * Hdim;
  const float* sc = mod + b * ModW + sc_off * Hdim;
  f16* o = o16 + (size_t)row * Hdim;
  for (int i = tid; i < Hdim; i += 256)
    o[i] = __float2half((xr[i] - mu) * rstd * (1.f + sc[i]) + sh[i]);
}

// ------------------- tensor-core GEMM (NT, fp16) ----------------------------
__device__ __forceinline__ float gelu_tanh(float v) {
  const float c = 0.7978845608028654f;
  return 0.5f * v * (1.f + tanhf(c * (v + 0.044715f * v * v * v)));
}

#define EPI_BIAS    0
#define EPI_GELU    1
#define EPI_RESGATE 2

__device__ __forceinline__ void mma_f16(float c[4], const uint32_t a[4],
                                        const uint32_t b[2]) {
  asm volatile(
      "mma.sync.aligned.m16n8k16.row.col.f32.f16.f16.f32 "
      "{%0,%1,%2,%3}, {%4,%5,%6,%7}, {%8,%9}, {%0,%1,%2,%3};"
      : "+f"(c[0]), "+f"(c[1]), "+f"(c[2]), "+f"(c[3])
      : "r"(a[0]), "r"(a[1]), "r"(a[2]), "r"(a[3]), "r"(b[0]), "r"(b[1]));
}

__device__ __forceinline__ void ldsm4(uint32_t r[4], uint32_t addr) {
  asm volatile("ldmatrix.sync.aligned.m8n8.x4.shared.b16 {%0,%1,%2,%3}, [%4];"
               : "=r"(r[0]), "=r"(r[1]), "=r"(r[2]), "=r"(r[3]) : "r"(addr));
}
__device__ __forceinline__ void ldsm4t(uint32_t r[4], uint32_t addr) {
  asm volatile(
      "ldmatrix.sync.aligned.m8n8.x4.trans.shared.b16 {%0,%1,%2,%3}, [%4];"
      : "=r"(r[0]), "=r"(r[1]), "=r"(r[2]), "=r"(r[3]) : "r"(addr));
}

__device__ __forceinline__ void cp16(uint32_t dst, const void* src, bool p) {
  int sz = p ? 16 : 0;
  asm volatile("cp.async.cg.shared.global [%0], [%1], 16, %2;\n"
               :: "r"(dst), "l"(src), "r"(sz));
}

// K-tile 64: plane = 128 rows x 144B (128B data + 16B pad).
#define PL_B    18432
#define STAGE_B (2 * PL_B)       // A, B = 36864
#define GSMEM   (2 * STAGE_B)    // 73728

template <int EPI, bool OUTF, bool OUTB>
__global__ __launch_bounds__(256, 2) void gemm_tc(
    const f16* __restrict__ A, const f16* __restrict__ W,
    const float* __restrict__ bias, const float* __restrict__ res,
    const float* __restrict__ gate, float* __restrict__ C,
    f16* __restrict__ C16,
    int M, int N, int K) {
  extern __shared__ char smc[];
  uint32_t sbase = (uint32_t)__cvta_generic_to_shared(smc);
  int tid = threadIdx.x;
  int warp = tid >> 5, lane = tid & 31;
  int wm = warp & 3, wn = warp >> 2;     // 4 warps M x 2 warps N
  int m0 = blockIdx.y << 7, n0 = blockIdx.x << 7;

  float acc[2][8][4];
#pragma unroll
  for (int mt = 0; mt < 2; mt++)
#pragma unroll
    for (int nt = 0; nt < 8; nt++)
#pragma unroll
      for (int f = 0; f < 4; f++) acc[mt][nt][f] = 0.f;

  int lq = lane & 7, lb = (lane >> 3) & 1, lh = lane >> 4;
  uint32_t offA[2], offB[4];
#pragma unroll
  for (int mt = 0; mt < 2; mt++)
    offA[mt] = (uint32_t)((wm * 32 + mt * 16 + lq + lb * 8) * 144 + lh * 16);
#pragma unroll
  for (int j = 0; j < 4; j++)
    offB[j] = (uint32_t)(PL_B +
                         (wn * 64 + j * 16 + lq + lh * 8) * 144 + lb * 16);

  const int nk = K >> 6;

  // 2048 chunks/stage: A rows (1024) then B rows (1024).
  auto issue = [&](int kt, int s) {
    uint32_t st = sbase + s * STAGE_B;
    int k0 = kt << 6;
#pragma unroll
    for (int i = 0; i < 8; i++) {
      int idx = tid + (i << 8);
      int pl = idx >> 10;          // 0=A, 1=B
      int cc = idx & 1023;
      int row = cc >> 3, ch = cc & 7;
      uint32_t d = st + pl * PL_B + row * 144 + ch * 16;
      const f16* src;
      bool ok = true;
      if (pl == 0) {
        int gm = m0 + row;
        ok = gm < M;
        src = A + (size_t)(ok ? gm : 0) * K + k0 + ch * 8;
      } else {
        src = W + (size_t)(n0 + row) * K + k0 + ch * 8;
      }
      cp16(d, src, ok);
    }
    asm volatile("cp.async.commit_group;\n");
  };

  issue(0, 0);
  for (int kt = 0; kt < nk; kt++) {
    int s = kt & 1;
    if (kt + 1 < nk) {
      issue(kt + 1, s ^ 1);
      asm volatile("cp.async.wait_group 1;\n");
    } else {
      asm volatile("cp.async.wait_group 0;\n");
    }
    __syncthreads();

    uint32_t sb = sbase + s * STAGE_B;
#pragma unroll
    for (int ks = 0; ks < 4; ks++) {
      uint32_t a_[2][4];
#pragma unroll
      for (int mt = 0; mt < 2; mt++)
        ldsm4(a_[mt], sb + offA[mt] + ks * 32);
#pragma unroll
      for (int jp = 0; jp < 2; jp++) {
        uint32_t b0[4], b1[4];
        ldsm4(b0, sb + offB[2 * jp]     + ks * 32);
        ldsm4(b1, sb + offB[2 * jp + 1] + ks * 32);
        float (*a0)[4] = acc[0], (*a1)[4] = acc[1];
        int q = 4 * jp;
        mma_f16(a0[q],     a_[0], b0);
        mma_f16(a0[q + 1], a_[0], b0 + 2);
        mma_f16(a1[q],     a_[1], b0);
        mma_f16(a1[q + 1], a_[1], b0 + 2);
        mma_f16(a0[q + 2], a_[0], b1);
        mma_f16(a0[q + 3], a_[0], b1 + 2);
        mma_f16(a1[q + 2], a_[1], b1);
        mma_f16(a1[q + 3], a_[1], b1 + 2);
      }
    }
    __syncthreads();
  }

  int g = lane >> 2, tg = lane & 3;
#pragma unroll
  for (int mt = 0; mt < 2; mt++) {
#pragma unroll
    for (int half = 0; half < 2; half++) {
      int m = m0 + wm * 32 + mt * 16 + g + half * 8;
      if (m >= M) continue;
      int bq = m >> 10;
#pragma unroll
      for (int nt = 0; nt < 8; nt++) {
        int n = n0 + wn * 64 + nt * 8 + tg * 2;
        float v0 = acc[mt][nt][half * 2 + 0];
        float v1 = acc[mt][nt][half * 2 + 1];
        if (bias) { v0 += bias[n]; v1 += bias[n + 1]; }
        if (EPI == EPI_GELU) { v0 = gelu_tanh(v0); v1 = gelu_tanh(v1); }
        if (EPI == EPI_RESGATE) {
          float g0 = 1.f, g1 = 1.f;
          if (gate) { g0 = gate[bq * ModW + n]; g1 = gate[bq * ModW + n + 1]; }
          v0 = res[(size_t)m * N + n] + g0 * v0;
          v1 = res[(size_t)m * N + n + 1] + g1 * v1;
        }
        if (OUTF)
          *(float2*)(C + (size_t)m * N + n) = make_float2(v0, v1);
        if (OUTB)
          *(f162*)(C16 + (size_t)m * N + n) = __floats2half2_rn(v0, v1);
      }
    }
  }
}

// ---------------- tensor-core flash attention (fp16) ------------------------
#define ARB   176
#define APL   (128 * ARB)
#define ATSM  (5 * APL)            // Q + 2 stages x (K,V)

__global__ __launch_bounds__(256) void attn_tc(
    const f16* __restrict__ Q, long long qbs, int ldq,
    const f16* __restrict__ Kp, const f16* __restrict__ Vp,
    long long kbs, int ldk,
    f16* __restrict__ O,
    int kv_len, float sl2e) {
  extern __shared__ char smb[];
  uint32_t sb = (uint32_t)__cvta_generic_to_shared(smb);
  int b = blockIdx.z, h = blockIdx.y;
  int m0 = blockIdx.x * 128;
  int tid = threadIdx.x, warp = tid >> 5, lane = tid & 31;
  int g = lane >> 2, tg = lane & 3;
  int lq = lane & 7, lb = (lane >> 3) & 1, lh = lane >> 4;

  const f16* Qb = Q  + (size_t)b * qbs + (size_t)m0 * ldq + h * HeadD;
  const f16* Kb = Kp + (size_t)b * kbs + h * HeadD;
  const f16* Vb = Vp + (size_t)b * kbs + h * HeadD;

  for (int i = tid; i < 640; i += 256) {
    int p = i >> 7, r = i & 127;
    uint32_t ad = sb + p * APL + r * ARB + 144;
    asm volatile("st.shared.v4.b32 [%0], {%1,%1,%1,%1};" :: "r"(ad), "r"(0));
    asm volatile("st.shared.v4.b32 [%0], {%1,%1,%1,%1};"
                 :: "r"(ad + 16), "r"(0));
  }

  for (int i = tid; i < 1152; i += 256) {
    int r = i / 9, ch = i % 9;
    cp16(sb + r * ARB + ch * 16, Qb + (size_t)r * ldq + ch * 8, true);
  }

  auto loadKV = [&](int j0, int s) {
    uint32_t st = sb + APL + s * 2 * APL;
    for (int i = tid; i < 1152; i += 256) {
      int r = i / 9, ch = i % 9;
      bool ok = (j0 + r) < kv_len;
      int rc = ok ? (j0 + r) : 0;
      size_t off = (size_t)rc * ldk + ch * 8;
      uint32_t d = st + r * ARB + ch * 16;
      cp16(d,       Kb + off, ok);
      cp16(d + APL, Vb + off, ok);
    }
    asm volatile("cp.async.commit_group;\n");
  };

  int iters = (kv_len + 127) >> 7;
  loadKV(0, 0);
  if (iters > 1) loadKV(128, 1);

  float m0r = -1e30f, m1r = -1e30f, ls0 = 0.f, ls1 = 0.f;
  float oacc[9][4];
#pragma unroll
  for (int nt = 0; nt < 9; nt++)
#pragma unroll
    for (int f = 0; f < 4; f++) oacc[nt][f] = 0.f;

  uint32_t offA = (uint32_t)((warp * 16 + lq + lb * 8) * ARB + lh * 16);
  uint32_t offB = (uint32_t)((lq + lh * 8) * ARB + lb * 16);
  uint32_t offV = (uint32_t)((lq + lb * 8) * ARB + lh * 16);

  for (int it = 0; it < iters; it++) {
    if (it + 1 < iters) {
      if (it > 0) loadKV((it + 1) * 128, (it + 1) & 1);
      asm volatile("cp.async.wait_group 1;\n");
    } else {
      asm volatile("cp.async.wait_group 0;\n");
    }
    __syncthreads();

    uint32_t kbse = sb + APL + (it & 1) * 2 * APL;

    float sa[16][4];
#pragma unroll
    for (int j = 0; j < 16; j++)
#pragma unroll
      for (int f = 0; f < 4; f++) sa[j][f] = 0.f;

#pragma unroll
    for (int ks = 0; ks < 5; ks++) {
      uint32_t a_[4];
      ldsm4(a_, sb + offA + ks * 32);
#pragma unroll
      for (int ntp = 0; ntp < 4; ntp++) {
        uint32_t b0[4], b1[4];
        ldsm4(b0, kbse + offB + (2 * ntp) * 16 * ARB + ks * 32);
        ldsm4(b1, kbse + offB + (2 * ntp + 1) * 16 * ARB + ks * 32);
        int q = 4 * ntp;
        mma_f16(sa[q],     a_, b0);
        mma_f16(sa[q + 1], a_, b0 + 2);
        mma_f16(sa[q + 2], a_, b1);
        mma_f16(sa[q + 3], a_, b1 + 2);
      }
    }

    int j0 = it * 128;
    bool msk = (j0 + 128) > kv_len;
    float mx0 = -1e30f, mx1 = -1e30f;
#pragma unroll
    for (int j = 0; j < 16; j++) {
#pragma unroll
      for (int e = 0; e < 4; e++) {
        float v = sa[j][e] * sl2e;
        if (msk) {
          int col = j * 8 + 2 * tg + (e & 1);
          if (j0 + col >= kv_len) v = -1e30f;
        }
        sa[j][e] = v;
      }
      mx0 = fmaxf(mx0, fmaxf(sa[j][0], sa[j][1]));
      mx1 = fmaxf(mx1, fmaxf(sa[j][2], sa[j][3]));
    }
    mx0 = fmaxf(mx0, __shfl_xor_sync(0xffffffffu, mx0, 1));
    mx0 = fmaxf(mx0, __shfl_xor_sync(0xffffffffu, mx0, 2));
    mx1 = fmaxf(mx1, __shfl_xor_sync(0xffffffffu, mx1, 1));
    mx1 = fmaxf(mx1, __shfl_xor_sync(0xffffffffu, mx1, 2));
    float mn0 = fmaxf(m0r, mx0), mn1 = fmaxf(m1r, mx1);
    float al0 = ex2(m0r - mn0), al1 = ex2(m1r - mn1);
    m0r = mn0; m1r = mn1;

    float s0 = 0.f, s1 = 0.f;
#pragma unroll
    for (int j = 0; j < 16; j++) {
      float p0 = ex2(sa[j][0] - mn0), p1 = ex2(sa[j][1] - mn0);
      float p2 = ex2(sa[j][2] - mn1), p3 = ex2(sa[j][3] - mn1);
      sa[j][0] = p0; sa[j][1] = p1; sa[j][2] = p2; sa[j][3] = p3;
      s0 += p0 + p1; s1 += p2 + p3;
    }
    s0 += __shfl_xor_sync(0xffffffffu, s0, 1);
    s0 += __shfl_xor_sync(0xffffffffu, s0, 2);
    s1 += __shfl_xor_sync(0xffffffffu, s1, 1);
    s1 += __shfl_xor_sync(0xffffffffu, s1, 2);
    ls0 = ls0 * al0 + s0;
    ls1 = ls1 * al1 + s1;
#pragma unroll
    for (int nt = 0; nt < 9; nt++) {
      oacc[nt][0] *= al0; oacc[nt][1] *= al0;
      oacc[nt][2] *= al1; oacc[nt][3] *= al1;
    }

    uint32_t vbse = kbse + APL;
#pragma unroll
    for (int kc = 0; kc < 8; kc++) {
      uint32_t pa[4];
#pragma unroll
      for (int jj = 0; jj < 2; jj++) {
        int j = 2 * kc + jj;
        pa[2 * jj]     = pack_f16x2(sa[j][0], sa[j][1]);
        pa[2 * jj + 1] = pack_f16x2(sa[j][2], sa[j][3]);
      }
#pragma unroll
      for (int npp = 0; npp < 2; npp++) {
        int np0 = 2 * npp, np1 = 2 * npp + 1;
        uint32_t v0[4], v1[4];
        ldsm4t(v0, vbse + offV + kc * 16 * ARB + np0 * 32);
        ldsm4t(v1, vbse + offV + kc * 16 * ARB + np1 * 32);
        mma_f16(oacc[2 * np0],     pa, v0);
        mma_f16(oacc[2 * np0 + 1], pa, v0 + 2);
        mma_f16(oacc[2 * np1],     pa, v1);
        mma_f16(oacc[2 * np1 + 1], pa, v1 + 2);
      }
      {
        uint32_t v4[4];
        ldsm4t(v4, vbse + offV + kc * 16 * ARB + 4 * 32);
        mma_f16(oacc[8], pa, v4);
      }
    }
    __syncthreads();
  }

  float inv0 = 1.f / ls0, inv1 = 1.f / ls1;
  int r0 = m0 + warp * 16 + g, r1 = r0 + 8;
  size_t base0 = ((size_t)b * Ntok + r0) * Hdim + h * HeadD;
  size_t base1 = ((size_t)b * Ntok + r1) * Hdim + h * HeadD;
#pragma unroll
  for (int nt = 0; nt < 9; nt++) {
    int col = nt * 8 + 2 * tg;
    *(f162*)(O + base0 + col) =
        __floats2half2_rn(oacc[nt][0] * inv0, oacc[nt][1] * inv0);
    *(f162*)(O + base1 + col) =
        __floats2half2_rn(oacc[nt][2] * inv1, oacc[nt][3] * inv1);
  }
}

// ------------------------------ launcher -----------------------------------
static float* sym_f(const void* s) { void* p; cudaGetSymbolAddress(&p, s); return (float*)p; }
static f16*   sym_h(const void* s) { void* p; cudaGetSymbolAddress(&p, s); return (f16*)p; }

extern "C" void kernel_launch(void* const* d_in, const int* in_sizes, int n_in,
                              void* d_out, int out_size) {
  (void)in_sizes; (void)n_in; (void)out_size;
  const float* x        = (const float*)d_in[0];
  const float* c        = (const float*)d_in[1];
  const float* t_emb    = (const float*)d_in[2];
  const float* qkv_w    = (const float*)d_in[3];
  const float* qkv_b    = (const float*)d_in[4];
  const float* proj_w   = (const float*)d_in[5];
  const float* proj_b   = (const float*)d_in[6];
  const float* to_q_w   = (const float*)d_in[7];
  const float* to_k_w   = (const float*)d_in[8];
  const float* to_v_w   = (const float*)d_in[9];
  const float* to_out_w = (const float*)d_in[10];
  const float* to_out_b = (const float*)d_in[11];
  const float* mlp_w1   = (const float*)d_in[12];
  const float* mlp_b1   = (const float*)d_in[13];
  const float* mlp_w2   = (const float*)d_in[14];
  const float* mlp_b2   = (const float*)d_in[15];
  const float* ada_w    = (const float*)d_in[16];
  const float* ada_b    = (const float*)d_in[17];
  float* out = (float*)d_out;

  float *mod = sym_f(&g_mod), *xb = sym_f(&g_xb);
  f16 *ln = sym_h(&g_ln), *at = sym_h(&g_at), *xbh = sym_h(&g_xbh);
  f16 *qkv = sym_h(&g_qkv), *kv = sym_h(&g_kv), *hid = sym_h(&g_hid);
  f16 *cc = sym_h(&g_c);
  f16 *wqkv = sym_h(&g_wqkv), *wpr = sym_h(&g_wpr), *wq = sym_h(&g_wq);
  f16 *wkv = sym_h(&g_wkv), *wo = sym_h(&g_wo);
  f16 *w1 = sym_h(&g_w1), *w2 = sym_h(&g_w2);

  cudaFuncSetAttribute(attn_tc,
                       cudaFuncAttributeMaxDynamicSharedMemorySize, ATSM);
#define SETSM(k) cudaFuncSetAttribute(k, \
    cudaFuncAttributeMaxDynamicSharedMemorySize, GSMEM)
  SETSM((gemm_tc<EPI_BIAS, false, true>));
  SETSM((gemm_tc<EPI_GELU, false, true>));
  SETSM((gemm_tc<EPI_RESGATE, true, true>));
  SETSM((gemm_tc<EPI_RESGATE, true, false>));
#undef SETSM

  const float sl2e = (1.f / sqrtf((float)HeadD)) * 1.4426950408889634f;

  // conversions: 8 weight tensors + context, all single fp16
  {
    CvtJobs J;
    const float* s[9] = {qkv_w, proj_w, to_q_w, to_k_w, to_v_w,
                         to_out_w, mlp_w1, mlp_w2, c};
    f16* dd[9] = {wqkv, wpr, wq, wkv, wkv + Hdim * CtxD, wo, w1, w2, cc};
    int nn[9] = {3 * Hdim * Hdim, Hdim * Hdim, Hdim * Hdim, Hdim * CtxD,
                 Hdim * CtxD, Hdim * Hdim, MlpD * Hdim, Hdim * MlpD,
                 Crows * CtxD};
    for (int i = 0; i < 9; i++) { J.src[i] = s[i]; J.dst[i] = dd[i];
                                  J.n[i] = nn[i]; }
    dim3 g((MlpD * Hdim / 4 + 255) / 256, 9);
    cvt_all_kernel<<<g, 256>>>(J);
  }
  ada_kernel<<<ModW / 128, 128>>>(t_emb, ada_w, ada_b, mod);
  ln_mod_kernel<<<Mrows, 256>>>(x, mod, 0, 1, ln);
  // qkv
  {
    dim3 g(3 * Hdim / 128, Mrows / 128);
    gemm_tc<EPI_BIAS, false, true><<<g, 256, GSMEM>>>(
        ln, wqkv, qkv_b, nullptr, nullptr,
        nullptr, qkv, Mrows, 3 * Hdim, Hdim);
  }
  // self-attention
  {
    dim3 g(Ntok / 128, NHead, Bsz);
    attn_tc<<<g, 256, ATSM>>>(
        qkv, (long long)Ntok * 3 * Hdim, 3 * Hdim,
        qkv + Hdim, qkv + 2 * Hdim, (long long)Ntok * 3 * Hdim, 3 * Hdim,
        at, Ntok, sl2e);
  }
  // proj + gated residual; cross-attn Q
  {
    dim3 g(Hdim / 128, Mrows / 128);
    gemm_tc<EPI_RESGATE, true, true><<<g, 256, GSMEM>>>(
        at, wpr, proj_b, x, mod + 2 * Hdim,
        xb, xbh, Mrows, Hdim, Hdim);
    gemm_tc<EPI_BIAS, false, true><<<g, 256, GSMEM>>>(
        xbh, wq, nullptr, nullptr, nullptr,
        nullptr, ln, Mrows, Hdim, Hdim);
  }
  // cross-attn K|V (merged)
  {
    dim3 g(KVW / 128, (Crows + 127) / 128);
    gemm_tc<EPI_BIAS, false, true><<<g, 256, GSMEM>>>(
        cc, wkv, nullptr, nullptr, nullptr,
        nullptr, kv, Crows, KVW, CtxD);
  }
  // cross-attention
  {
    dim3 g(Ntok / 128, NHead, Bsz);
    attn_tc<<<g, 256, ATSM>>>(
        ln, (long long)Ntok * Hdim, Hdim,
        kv, kv + Hdim, (long long)CtxT * KVW, KVW,
        at, CtxT, sl2e);
  }
  // to_out + residual
  {
    dim3 g(Hdim / 128, Mrows / 128);
    gemm_tc<EPI_RESGATE, true, false><<<g, 256, GSMEM>>>(
        at, wo, to_out_b, xb, nullptr,
        xb, nullptr, Mrows, Hdim, Hdim);
  }
  ln_mod_kernel<<<Mrows, 256>>>(xb, mod, 3, 4, ln);
  // MLP
  {
    dim3 g1(MlpD / 128, Mrows / 128);
    gemm_tc<EPI_GELU, false, true><<<g1, 256, GSMEM>>>(
        ln, w1, mlp_b1, nullptr, nullptr,
        nullptr, hid, Mrows, MlpD, Hdim);
    dim3 g2(Hdim / 128, Mrows / 128);
    gemm_tc<EPI_RESGATE, true, false><<<g2, 256, GSMEM>>>(
        hid, w2, mlp_b2, xb, mod + 5 * Hdim,
        out, nullptr, Mrows, Hdim, MlpD);
  }
}